// round 1
// baseline (speedup 1.0000x reference)
#include <cuda_runtime.h>
#include <cstdint>

// Emu3 VQ vector quantizer.
// x: (1,2,4,64,64) fp32 -> N=8192 rows of C=4.  E: (32768,4) fp32.
// Outputs (float32, concatenated): z_q_st (32768) | qloss (1) | codes (8192).
//
// Exact-rounding strategy: reference computes per (n,k)
//   c   = fp32 dot (fma chain)
//   t   = fl(xx_n + ee_k)
//   d   = fl(t - fl(2*c))          (2*c exact, so == fma(c,-2,t))
// and argmin with first-index tie-break. We rank by a cheap packed-f32x2
// proxy (max of c) and exactly re-evaluate d only for margin-triggered
// chunks; global combine via atomicMin on (d_bits<<32 | k), which encodes
// first-index tie-break for positive d.

#define N_ROWS  8192
#define N_CODES 32768
#define ROWTILES 8
#define KSPLIT  37
#define KPER    896      // multiple of 32; 37*896 >= 32768
#define CHUNK   32

__device__ unsigned long long g_best[N_ROWS];
__device__ __align__(16) float g_eT[4][N_CODES];
__device__ float g_ee[N_CODES];
__device__ float g_xx[N_ROWS];
__device__ float g_lp[32];

// ---------- packed f32x2 helpers ----------
__device__ __forceinline__ unsigned long long pk2(float lo, float hi) {
    unsigned long long r;
    unsigned int l = __float_as_uint(lo), h = __float_as_uint(hi);
    asm("mov.b64 %0, {%1, %2};" : "=l"(r) : "r"(l), "r"(h));
    return r;
}
__device__ __forceinline__ void upk2(unsigned long long v, float& lo, float& hi) {
    unsigned int l, h;
    asm("mov.b64 {%0, %1}, %2;" : "=r"(l), "=r"(h) : "l"(v));
    lo = __uint_as_float(l); hi = __uint_as_float(h);
}
__device__ __forceinline__ unsigned long long mul2(unsigned long long a, unsigned long long b) {
    unsigned long long r;
    asm("mul.rn.f32x2 %0, %1, %2;" : "=l"(r) : "l"(a), "l"(b));
    return r;
}
__device__ __forceinline__ unsigned long long fma2(unsigned long long a, unsigned long long b, unsigned long long c) {
    unsigned long long r;
    asm("fma.rn.f32x2 %0, %1, %2, %3;" : "=l"(r) : "l"(a), "l"(b), "l"(c));
    return r;
}

// ---------- prep: transpose E, ||e||^2, ||x||^2, init keys ----------
__global__ void prep_kernel(const float* __restrict__ x, const float* __restrict__ E) {
    int i = blockIdx.x * blockDim.x + threadIdx.x;
    if (i < N_CODES) {
        float4 e = reinterpret_cast<const float4*>(E)[i];
        g_eT[0][i] = e.x; g_eT[1][i] = e.y; g_eT[2][i] = e.z; g_eT[3][i] = e.w;
        float s = __fadd_rn(__fadd_rn(__fadd_rn(__fmul_rn(e.x, e.x), __fmul_rn(e.y, e.y)),
                                      __fmul_rn(e.z, e.z)), __fmul_rn(e.w, e.w));
        g_ee[i] = s;
    }
    if (i < N_ROWS) {
        int bt = i >> 12, hw = i & 4095;
        const float* xb = x + (bt * 4) * 4096 + hw;
        float x0 = xb[0], x1 = xb[4096], x2 = xb[2 * 4096], x3 = xb[3 * 4096];
        float s = __fadd_rn(__fadd_rn(__fadd_rn(__fmul_rn(x0, x0), __fmul_rn(x1, x1)),
                                      __fmul_rn(x2, x2)), __fmul_rn(x3, x3));
        g_xx[i] = s;
        g_best[i] = 0xFFFFFFFFFFFFFFFFull;
    }
}

// ---------- main argmin ----------
__global__ void __launch_bounds__(256) argmin_kernel(const float* __restrict__ x) {
    const int tid = threadIdx.x;
    const int rbase = blockIdx.x * 1024 + tid * 4;
    const int split = blockIdx.y;

    float xs[4][4];
    unsigned long long xd[4][4];
    float xx[4], marg[4], cmax[4], bd[4];
    int bi[4];

#pragma unroll
    for (int r = 0; r < 4; r++) {
        int row = rbase + r;
        int bt = row >> 12, hw = row & 4095;
        const float* xb = x + (bt * 4) * 4096 + hw;
#pragma unroll
        for (int c = 0; c < 4; c++) {
            float v = xb[c * 4096];
            xs[r][c] = v;
            xd[r][c] = pk2(v, v);
        }
        xx[r]   = g_xx[row];
        // margin in c-units: covers d quantization (<= ulp(xx)) + ee variation
        marg[r] = __fmaf_rn(xx[r], 1e-6f, 2e-8f);
        cmax[r] = -3.0e38f;
        bd[r]   = 3.0e38f;
        bi[r]   = 0;
    }

    const int k0 = split * KPER;
    const int k1 = min(k0 + KPER, N_CODES);
    const float4* e0p = reinterpret_cast<const float4*>(g_eT[0]);
    const float4* e1p = reinterpret_cast<const float4*>(g_eT[1]);
    const float4* e2p = reinterpret_cast<const float4*>(g_eT[2]);
    const float4* e3p = reinterpret_cast<const float4*>(g_eT[3]);

    for (int kc = k0; kc < k1; kc += CHUNK) {
        float thr[4], mch[4];
#pragma unroll
        for (int r = 0; r < 4; r++) { thr[r] = cmax[r] - marg[r]; mch[r] = thr[r]; }

#pragma unroll
        for (int g = 0; g < CHUNK / 4; g++) {
            int kg = (kc >> 2) + g;
            float4 a0 = e0p[kg], a1 = e1p[kg], a2 = e2p[kg], a3 = e3p[kg];
            unsigned long long E0[2] = { pk2(a0.x, a0.y), pk2(a0.z, a0.w) };
            unsigned long long E1[2] = { pk2(a1.x, a1.y), pk2(a1.z, a1.w) };
            unsigned long long E2[2] = { pk2(a2.x, a2.y), pk2(a2.z, a2.w) };
            unsigned long long E3[2] = { pk2(a3.x, a3.y), pk2(a3.z, a3.w) };
#pragma unroll
            for (int p = 0; p < 2; p++) {
#pragma unroll
                for (int r = 0; r < 4; r++) {
                    unsigned long long c2 = mul2(xd[r][0], E0[p]);
                    c2 = fma2(xd[r][1], E1[p], c2);
                    c2 = fma2(xd[r][2], E2[p], c2);
                    c2 = fma2(xd[r][3], E3[p], c2);
                    float lo, hi; upk2(c2, lo, hi);
                    mch[r] = fmaxf(mch[r], fmaxf(lo, hi));
                }
            }
        }

#pragma unroll
        for (int r = 0; r < 4; r++) {
            if (mch[r] > thr[r]) {
                // rare: exact re-evaluation of this chunk with reference rounding
                float xr0 = xs[r][0], xr1 = xs[r][1], xr2 = xs[r][2], xr3 = xs[r][3];
                float txx = xx[r];
                float lbd = bd[r]; int lbi = bi[r];
                for (int kk = kc; kk < kc + CHUNK; kk++) {
                    float c = __fmul_rn(xr0, g_eT[0][kk]);
                    c = __fmaf_rn(xr1, g_eT[1][kk], c);
                    c = __fmaf_rn(xr2, g_eT[2][kk], c);
                    c = __fmaf_rn(xr3, g_eT[3][kk], c);
                    float t = __fadd_rn(txx, g_ee[kk]);
                    float d = __fmaf_rn(c, -2.0f, t);   // == fl(t - 2c), 2c exact
                    if (d < lbd) { lbd = d; lbi = kk; }
                }
                bd[r] = lbd; bi[r] = lbi;
                cmax[r] = fmaxf(cmax[r], mch[r]);
            }
        }
    }

#pragma unroll
    for (int r = 0; r < 4; r++) {
        unsigned long long key =
            ((unsigned long long)__float_as_uint(bd[r]) << 32) | (unsigned int)bi[r];
        atomicMin(&g_best[rbase + r], key);
    }
}

// ---------- finalize: gather z_q, straight-through, codes, loss partials ----------
__global__ void finalize_kernel(const float* __restrict__ x, const float* __restrict__ E,
                                float* __restrict__ out, int out_size) {
    __shared__ float red[256];
    int n = blockIdx.x * 256 + threadIdx.x;
    unsigned long long key = g_best[n];
    int k = (int)(unsigned int)(key & 0xFFFFFFFFull);
    float4 e = reinterpret_cast<const float4*>(E)[k];
    float ev[4] = { e.x, e.y, e.z, e.w };
    int bt = n >> 12, hw = n & 4095;
    int xb = (bt * 4) * 4096 + hw;
    float lsum = 0.0f;
#pragma unroll
    for (int c = 0; c < 4; c++) {
        int idx = xb + c * 4096;
        float xi = x[idx];
        float diff = __fadd_rn(ev[c], -xi);          // fl(z_q - x)
        if (idx < out_size) out[idx] = __fadd_rn(xi, diff);  // x + sg(z_q - x)
        lsum = __fmaf_rn(diff, diff, lsum);
    }
    int ci = 32769 + n;
    if (ci < out_size) out[ci] = (float)k;

    red[threadIdx.x] = lsum;
    __syncthreads();
    for (int s = 128; s > 0; s >>= 1) {
        if (threadIdx.x < s) red[threadIdx.x] += red[threadIdx.x + s];
        __syncthreads();
    }
    if (threadIdx.x == 0) g_lp[blockIdx.x] = red[0];
}

__global__ void loss_kernel(float* __restrict__ out, int out_size) {
    if (threadIdx.x == 0 && 32768 < out_size) {
        float s = 0.0f;
        for (int i = 0; i < 32; i++) s += g_lp[i];
        float m = s * (1.0f / 32768.0f);             // exact /2^15
        out[32768] = __fadd_rn(m, __fmul_rn(0.1f, m));  // mean + BETA*mean
    }
}

extern "C" void kernel_launch(void* const* d_in, const int* in_sizes, int n_in,
                              void* d_out, int out_size) {
    const float* x = (const float*)d_in[0];
    const float* E = (const float*)d_in[1];
    if (n_in >= 2 && in_sizes[0] > in_sizes[1]) {   // defensive: x is the smaller tensor
        x = (const float*)d_in[1];
        E = (const float*)d_in[0];
    }
    float* out = (float*)d_out;

    prep_kernel<<<128, 256>>>(x, E);
    dim3 grid(ROWTILES, KSPLIT);
    argmin_kernel<<<grid, 256>>>(x);
    finalize_kernel<<<32, 256>>>(x, E, out, out_size);
    loss_kernel<<<1, 32>>>(out, out_size);
}